// round 11
// baseline (speedup 1.0000x reference)
#include <cuda_runtime.h>

// x: (16, 256, 128, 128) fp32 -> 2x2 block sum * 0.5, then 2x2 NN upsample.
//
// R11: R9's best-measured form (float4 lane-contiguous, 4 front-batched
// LDG.128 MLP=4 + 4 STG.128, .cs evict-first) with ONE variable changed:
// block size 512 -> 1024, continuing the reproducible geometry trend
// (256->512 gave -0.3us via shallower cross-CTA L1tex queues / smaller
// wave-tail spread).
//
// Each thread: one float4 column slot x two row pairs (4 consecutive rows).
// Row = 128 floats = 32 float4. 16*256*32 groups x 32 slots = 4,194,304
// threads = 4096 CTAs @ 1024.

__global__ void __launch_bounds__(1024) wfdm_kernel(
    const float4* __restrict__ in, float4* __restrict__ out)
{
    int tid = blockIdx.x * blockDim.x + threadIdx.x;

    int col   = tid & 31;      // float4 slot within row (0..31), lane-contiguous
    int group = tid >> 5;      // group of 4 rows (2 row pairs)

    int base = group * 128 + col;   // 4 rows * 32 float4/row

    // Front-batched independent loads, all lane-stride-1: MLP = 4
    float4 t0 = __ldcs(&in[base]);         // row 4g
    float4 b0 = __ldcs(&in[base + 32]);    // row 4g+1
    float4 t1 = __ldcs(&in[base + 64]);    // row 4g+2
    float4 b1 = __ldcs(&in[base + 96]);    // row 4g+3

    // Row pair 0
    float s0 = (t0.x + t0.y + b0.x + b0.y) * 0.5f;
    float s1 = (t0.z + t0.w + b0.z + b0.w) * 0.5f;
    // Row pair 1
    float s2 = (t1.x + t1.y + b1.x + b1.y) * 0.5f;
    float s3 = (t1.z + t1.w + b1.z + b1.w) * 0.5f;

    float4 o0 = make_float4(s0, s0, s1, s1);
    float4 o1 = make_float4(s2, s2, s3, s3);

    __stcs(&out[base],      o0);
    __stcs(&out[base + 32], o0);
    __stcs(&out[base + 64], o1);
    __stcs(&out[base + 96], o1);
}

extern "C" void kernel_launch(void* const* d_in, const int* in_sizes, int n_in,
                              void* d_out, int out_size)
{
    const float4* in = (const float4*)d_in[0];
    float4* out = (float4*)d_out;

    // total threads = elements / 16 (each thread covers 16 floats)
    int total = out_size / 16;   // 16*256*128*128 / 16 = 4,194,304
    int threads = 1024;
    int blocks = total / threads;  // exact: 4096
    wfdm_kernel<<<blocks, threads>>>(in, out);
}

// round 12
// speedup vs baseline: 1.0059x; 1.0059x over previous
#include <cuda_runtime.h>

// x: (16, 256, 128, 128) fp32 -> 2x2 block sum * 0.5, then 2x2 NN upsample.
//
// FINAL (R9 confirmation re-bench): measured optimum across 11 rounds.
//   - float4 lane-contiguous accesses (perfect 128B/warp-quarter coalescing)
//   - 4 front-batched LDG.128 (MLP=4) + 4 STG.128 per thread
//   - .cs evict-first hints (537 MB streams through 126 MB L2 exactly once)
//   - 512-thread blocks (geometry sweet spot: 256->82.0, 512->81.7, 1024->82.3)
//
// Landscape: all coalesced variants sit at 80-82% DRAM (~6.4-6.5 TB/s), the
// GB300 mixed read/write HBM3e stream ceiling. Compute pipes <6%, issue ~8%:
// nothing else is binding.
//
// Each thread: one float4 column slot x two row pairs (4 consecutive rows).
// Row = 128 floats = 32 float4. 16*256*32 groups x 32 slots = 4,194,304
// threads = 8192 CTAs @ 512.

__global__ void __launch_bounds__(512) wfdm_kernel(
    const float4* __restrict__ in, float4* __restrict__ out)
{
    int tid = blockIdx.x * blockDim.x + threadIdx.x;

    int col   = tid & 31;      // float4 slot within row (0..31), lane-contiguous
    int group = tid >> 5;      // group of 4 rows (2 row pairs)

    int base = group * 128 + col;   // 4 rows * 32 float4/row

    // Front-batched independent loads, all lane-stride-1: MLP = 4
    float4 t0 = __ldcs(&in[base]);         // row 4g
    float4 b0 = __ldcs(&in[base + 32]);    // row 4g+1
    float4 t1 = __ldcs(&in[base + 64]);    // row 4g+2
    float4 b1 = __ldcs(&in[base + 96]);    // row 4g+3

    // Row pair 0
    float s0 = (t0.x + t0.y + b0.x + b0.y) * 0.5f;
    float s1 = (t0.z + t0.w + b0.z + b0.w) * 0.5f;
    // Row pair 1
    float s2 = (t1.x + t1.y + b1.x + b1.y) * 0.5f;
    float s3 = (t1.z + t1.w + b1.z + b1.w) * 0.5f;

    float4 o0 = make_float4(s0, s0, s1, s1);
    float4 o1 = make_float4(s2, s2, s3, s3);

    __stcs(&out[base],      o0);
    __stcs(&out[base + 32], o0);
    __stcs(&out[base + 64], o1);
    __stcs(&out[base + 96], o1);
}

extern "C" void kernel_launch(void* const* d_in, const int* in_sizes, int n_in,
                              void* d_out, int out_size)
{
    const float4* in = (const float4*)d_in[0];
    float4* out = (float4*)d_out;

    // total threads = elements / 16 (each thread covers 16 floats)
    int total = out_size / 16;   // 16*256*128*128 / 16 = 4,194,304
    int threads = 512;
    int blocks = total / threads;  // exact: 8192
    wfdm_kernel<<<blocks, threads>>>(in, out);
}